// round 15
// baseline (speedup 1.0000x reference)
#include <cuda_runtime.h>
#include <math.h>

// Problem constants (fixed: features [512,384] f32, labels [512] i32)
#define NQ 512
#define DIM 384
#define KSPLIT 6
#define KCH 64               // K per gram job
#define TS 64                // gram tile size (M and N)
#define KC 16                // gram k-chunk
#define NJOBS (KSPLIT * (NQ / TS) * (NQ / TS))   // 6*8*8 = 384
#define SCALE 50.0f          // 1/(2*t2): sigmoid(z) = 0.5 + 0.5*tanh(z/2)
#define KSEL 6.0f            // K = 5 + 1

// Scratch (no allocations allowed anywhere)
__device__ float g_part[KSPLIT * NQ * NQ];  // partial Gram matrices (6 MB, stays in L2)
__device__ float g_sqp[KSPLIT * NQ];        // partial diagonal (squared norms)
__device__ float g_prec[NQ];                // per-query precision sums
__device__ unsigned int g_bar = 0;          // grid barrier arrivals (reset by last block)
__device__ unsigned int g_count = 0;        // per-query completion tickets (reset too)

__device__ __forceinline__ float fast_tanh(float x) {
    float r;
    asm("tanh.approx.f32 %0, %1;" : "=f"(r) : "f"(x));
    return r;
}

// ---------------------------------------------------------------------------
// ONE persistent kernel. All blocks resident (grid = 3 * #SM, launch_bounds
// guarantees 3 blocks/SM by regs; smem ~19KB/block -> 57KB/SM fits).
//  Phase 1: grid-stride over 384 gram jobs (64x64 tile, K=64 split) -> g_part.
//  Grid barrier: threadfence + arrival counter + spin (all blocks resident).
//  Phase 2: grid-stride over 512 queries; direct tanh-rank of label-matched
//           items only (R14 math, 256-thread layout); fused loss reduction.
// ---------------------------------------------------------------------------
__global__ __launch_bounds__(256, 3) void fused_kernel(const float* __restrict__ F,
                                                       const int* __restrict__ labels,
                                                       float* __restrict__ out) {
    __shared__ float As[KC][TS + 4];   // gram [k][m]
    __shared__ float Bs[KC][TS + 4];   // gram [k][n]
    __shared__ float sq[NQ];           // summed squared norms
    __shared__ float va[NQ];           // val by gallery index
    __shared__ int   sl[NQ];           // labels staged
    __shared__ int   mlist[NQ];        // matched gallery indices
    __shared__ float cm[NQ];           // contrib per matched item
    __shared__ int   wcount[16];       // ballot counts (2 halves x 8 warps)
    __shared__ float ws[8];
    __shared__ int isLast;

    const int t   = threadIdx.x;
    const int wid = t >> 5;
    const int lid = t & 31;
    const unsigned GRID = gridDim.x;

    // ================= Phase 1: gram jobs (grid-stride) =================
    for (int job = blockIdx.x; job < NJOBS; job += GRID) {
        const int jz  = job >> 6;            // K split 0..5
        const int rem = job & 63;
        const int bm  = (rem >> 3) * TS;
        const int bn  = (rem & 7) * TS;
        const int kb  = jz * KCH;
        const int tr = t >> 4, tc = t & 15;
        const int lr = t >> 2, lc = (t & 3) * 4;

        float acc[4][4] = {};
        for (int k0 = kb; k0 < kb + KCH; k0 += KC) {
            float4 av = *reinterpret_cast<const float4*>(&F[(bm + lr) * DIM + k0 + lc]);
            As[lc + 0][lr] = av.x; As[lc + 1][lr] = av.y;
            As[lc + 2][lr] = av.z; As[lc + 3][lr] = av.w;
            float4 bv = *reinterpret_cast<const float4*>(&F[(bn + lr) * DIM + k0 + lc]);
            Bs[lc + 0][lr] = bv.x; Bs[lc + 1][lr] = bv.y;
            Bs[lc + 2][lr] = bv.z; Bs[lc + 3][lr] = bv.w;
            __syncthreads();
            #pragma unroll
            for (int kk = 0; kk < KC; kk++) {
                float4 a = *reinterpret_cast<const float4*>(&As[kk][4 * tr]);
                float4 b = *reinterpret_cast<const float4*>(&Bs[kk][4 * tc]);
                const float ar[4] = {a.x, a.y, a.z, a.w};
                const float br[4] = {b.x, b.y, b.z, b.w};
                #pragma unroll
                for (int i = 0; i < 4; i++)
                    #pragma unroll
                    for (int j = 0; j < 4; j++)
                        acc[i][j] = fmaf(ar[i], br[j], acc[i][j]);
            }
            __syncthreads();
        }
        float* dst = g_part + jz * (NQ * NQ);
        #pragma unroll
        for (int i = 0; i < 4; i++) {
            #pragma unroll
            for (int j = 0; j < 4; j++) {
                const int r = bm + 4 * tr + i;
                const int c = bn + 4 * tc + j;
                dst[r * NQ + c] = acc[i][j];
                if (r == c) g_sqp[jz * NQ + r] = acc[i][j];
            }
        }
    }

    // ================= Grid barrier (all blocks resident) =================
    __syncthreads();
    if (t == 0) {
        __threadfence();                       // release g_part/g_sqp writes
        atomicAdd(&g_bar, 1u);
        while (atomicAdd(&g_bar, 0u) < GRID) __nanosleep(64);
        __threadfence();
    }
    __syncthreads();

    // ================= Phase 2: queries (grid-stride) =================
    for (int q = blockIdx.x; q < NQ; q += (int)GRID) {
        // distances (2 gallery items per thread), labels, init
        float gq0 = 0.0f, gq1 = 0.0f;
        {
            float s0 = 0.0f, s1 = 0.0f;
            #pragma unroll
            for (int z = 0; z < KSPLIT; z++) {
                s0 += g_sqp[z * NQ + t];
                s1 += g_sqp[z * NQ + t + 256];
            }
            sq[t] = s0; sq[t + 256] = s1;
        }
        sl[t] = labels[t]; sl[t + 256] = labels[t + 256];
        cm[t] = 0.0f; cm[t + 256] = 0.0f;
        {
            const int od = q * NQ;
            #pragma unroll
            for (int z = 0; z < KSPLIT; z++) {
                gq0 += g_part[z * NQ * NQ + od + t];
                gq1 += g_part[z * NQ * NQ + od + t + 256];
            }
        }
        __syncthreads();
        const float sqq = sq[q];
        va[t]       = SCALE * sqrtf(fmaxf(sqq + sq[t]       - 2.0f * gq0, 0.0f));
        va[t + 256] = SCALE * sqrtf(fmaxf(sqq + sq[t + 256] - 2.0f * gq1, 0.0f));
        const int Lq = sl[q];

        // deterministic matched list: half 0 (g=t), then half 1 (g=t+256),
        // each in ascending index order -> globally ascending
        const bool f0 = (sl[t] == Lq);
        const bool f1 = (sl[t + 256] == Lq);
        const unsigned b0 = __ballot_sync(0xffffffffu, f0);
        const unsigned b1 = __ballot_sync(0xffffffffu, f1);
        if (lid == 0) { wcount[wid] = __popc(b0); wcount[8 + wid] = __popc(b1); }
        __syncthreads();                        // covers va + wcount
        int base0 = 0, base1 = 0, h1base = 0, M = 0;
        #pragma unroll
        for (int w = 0; w < 8; w++) {
            const int c0 = wcount[w], c1 = wcount[8 + w];
            base0 += (w < wid) ? c0 : 0;
            base1 += (w < wid) ? c1 : 0;
            h1base += c0;
            M += c0 + c1;
        }
        base1 += h1base;
        if (f0) mlist[base0 + __popc(b0 & ((1u << lid) - 1u))] = t;
        if (f1) mlist[base1 + __popc(b1 & ((1u << lid) - 1u))] = t + 256;
        __syncthreads();

        // direct rank per matched item: warp w handles items w, w+8, ...
        for (int m = wid; m < M; m += 8) {
            const float vm = va[mlist[m]];      // broadcast LDS
            float acc = 0.0f;
            #pragma unroll
            for (int i = 0; i < 16; i++) {
                acc += fast_tanh(vm - va[lid + 32 * i]);
            }
            #pragma unroll
            for (int o = 16; o; o >>= 1) acc += __shfl_xor_sync(0xffffffffu, acc, o);
            if (lid == 0) {
                const float rank = 0.5f * (float)NQ + 0.5f * acc;
                cm[m] = 1.0f / (1.0f + __expf(rank - KSEL));   // sigmoid(K - rank)
            }
        }
        __syncthreads();

        // block reduction of matched contribs (fixed tree)
        float contrib = cm[t] + cm[t + 256];
        #pragma unroll
        for (int o = 16; o; o >>= 1) contrib += __shfl_xor_sync(0xffffffffu, contrib, o);
        if (lid == 0) ws[wid] = contrib;
        __syncthreads();
        if (t == 0) {
            float s = 0.0f;
            #pragma unroll
            for (int w = 0; w < 8; w++) s += ws[w];
            g_prec[q] = s;
            __threadfence();
            const unsigned tk = atomicAdd(&g_count, 1u);
            isLast = (tk == NQ - 1) ? 1 : 0;
        }
        __syncthreads();

        // last-finishing query block: deterministic final reduction -> loss
        if (isLast) {
            __threadfence();
            float v = g_prec[t] + g_prec[t + 256];
            #pragma unroll
            for (int o = 16; o; o >>= 1) v += __shfl_xor_sync(0xffffffffu, v, o);
            if (lid == 0) ws[wid] = v;
            __syncthreads();
            if (t == 0) {
                float s = 0.0f;
                #pragma unroll
                for (int w = 0; w < 8; w++) s += ws[w];
                out[0] = 1.0f - s / (KSEL * (float)NQ);
                g_count = 0;   // reset for next graph replay
                g_bar = 0;     // (all blocks provably past the barrier here)
            }
        }
        __syncthreads();
    }
}

// ---------------------------------------------------------------------------
extern "C" void kernel_launch(void* const* d_in, const int* in_sizes, int n_in,
                              void* d_out, int out_size) {
    const float* F      = (const float*)d_in[0];
    const int*   labels = (const int*)d_in[1];
    float*       out    = (float*)d_out;

    static int nsm = 0;
    if (nsm == 0) {
        cudaDeviceGetAttribute(&nsm, cudaDevAttrMultiProcessorCount, 0);
        if (nsm <= 0) nsm = 148;
    }
    const int grid = 3 * nsm;   // __launch_bounds__(256,3) guarantees residency

    fused_kernel<<<grid, 256>>>(F, labels, out);
}